// round 4
// baseline (speedup 1.0000x reference)
#include <cuda_runtime.h>

// Problem constants (fixed by the dataset): N=50000, E=1600000, D=U=128.
// MAX_N padded to a multiple of 64 so the GEMM's OOB row reads stay in-bounds.
#define MAX_N 50048
#define MAX_E 1600000
#define D_DIM 128

// Scratch: __device__ globals (no allocations allowed anywhere).
__device__ int   g_counts[MAX_N];
__device__ int   g_offsets[MAX_N + 1];
__device__ int   g_cursor[MAX_N];
__device__ int2  g_edges[MAX_E];                    // (dst, weight-as-bits), sorted by src
__device__ float g_agg[(size_t)MAX_N * D_DIM];      // aggregated features

// ---------------------------------------------------------------------------
// 1) zero histogram
__global__ void init_counts_kernel(int N) {
    int i = blockIdx.x * blockDim.x + threadIdx.x;
    if (i < N) g_counts[i] = 0;
}

// 2) histogram of edge_src
__global__ void hist_kernel(const int* __restrict__ src, int E) {
    int e = blockIdx.x * blockDim.x + threadIdx.x;
    if (e < E) atomicAdd(&g_counts[src[e]], 1);
}

// 3) single-block exclusive scan -> g_offsets[0..N], and g_cursor = copy
__global__ void scan_kernel(int N) {
    __shared__ int s[1024];
    __shared__ int s_carry;
    const int tid = threadIdx.x;
    const int ITEMS = 16;
    const int CHUNK = 1024 * ITEMS;

    if (tid == 0) s_carry = 0;
    __syncthreads();

    for (int base = 0; base < N; base += CHUNK) {
        int vals[ITEMS];
        int local = 0;
        int start = base + tid * ITEMS;
#pragma unroll
        for (int i = 0; i < ITEMS; i++) {
            int idx = start + i;
            vals[i] = (idx < N) ? g_counts[idx] : 0;
            local += vals[i];
        }
        // Kogge-Stone inclusive scan of per-thread sums
        s[tid] = local;
        __syncthreads();
        int x = local;
        for (int off = 1; off < 1024; off <<= 1) {
            int y = (tid >= off) ? s[tid - off] : 0;
            __syncthreads();
            x += y;
            s[tid] = x;
            __syncthreads();
        }
        int running = s_carry;          // all threads read carry
        int pre = running + (x - local);  // exclusive prefix for this thread
#pragma unroll
        for (int i = 0; i < ITEMS; i++) {
            int idx = start + i;
            if (idx < N) { g_offsets[idx] = pre; g_cursor[idx] = pre; }
            pre += vals[i];
        }
        __syncthreads();                 // everyone done reading s_carry
        if (tid == 1023) s_carry = running + x;  // x@1023 == chunk total
        __syncthreads();
    }
    if (tid == 0) g_offsets[N] = s_carry;
}

// 4) scatter edges into CSR order (int atomics only)
__global__ void scatter_kernel(const int* __restrict__ src,
                               const int* __restrict__ dst,
                               const float* __restrict__ w, int E) {
    int e = blockIdx.x * blockDim.x + threadIdx.x;
    if (e < E) {
        int s = src[e];
        int pos = atomicAdd(&g_cursor[s], 1);
        g_edges[pos] = make_int2(dst[e], __float_as_int(w[e]));
    }
}

// 5) one warp per node: weighted mean of gathered feature rows (no float atomics)
__global__ void aggregate_kernel(const float* __restrict__ feat, int N) {
    int warp = (blockIdx.x * blockDim.x + threadIdx.x) >> 5;
    int lane = threadIdx.x & 31;
    if (warp >= N) return;

    int beg = g_offsets[warp];
    int end = g_offsets[warp + 1];

    const float4* f4 = (const float4*)feat;
    float ax = 0.f, ay = 0.f, az = 0.f, aw = 0.f;
    float den = 0.f;

    int j = beg;
    // 2-way unroll for MLP on the L2-resident gathers
    for (; j + 2 <= end; j += 2) {
        int2 e0 = g_edges[j];
        int2 e1 = g_edges[j + 1];
        float w0 = __int_as_float(e0.y);
        float w1 = __int_as_float(e1.y);
        float4 v0 = f4[(size_t)e0.x * 32 + lane];
        float4 v1 = f4[(size_t)e1.x * 32 + lane];
        ax = fmaf(w0, v0.x, ax); ax = fmaf(w1, v1.x, ax);
        ay = fmaf(w0, v0.y, ay); ay = fmaf(w1, v1.y, ay);
        az = fmaf(w0, v0.z, az); az = fmaf(w1, v1.z, az);
        aw = fmaf(w0, v0.w, aw); aw = fmaf(w1, v1.w, aw);
        den += w0 + w1;
    }
    if (j < end) {
        int2 e0 = g_edges[j];
        float w0 = __int_as_float(e0.y);
        float4 v0 = f4[(size_t)e0.x * 32 + lane];
        ax = fmaf(w0, v0.x, ax);
        ay = fmaf(w0, v0.y, ay);
        az = fmaf(w0, v0.z, az);
        aw = fmaf(w0, v0.w, aw);
        den += w0;
    }

    float inv = 1.0f / fmaxf(den, 1e-12f);
    float4 r = make_float4(ax * inv, ay * inv, az * inv, aw * inv);
    ((float4*)g_agg)[(size_t)warp * 32 + lane] = r;
}

// 6) out = relu(agg @ W + b)
// Block: 256 threads, tile 64 rows x 128 cols. W (64KB) + b in dynamic shared.
// Warp w handles 8 rows (broadcast A loads from L2); lane handles 4 cols.
__global__ void gemm_relu_kernel(const float* __restrict__ W,
                                 const float* __restrict__ b,
                                 float* __restrict__ out, int N) {
    extern __shared__ float sh[];
    float* Ws = sh;                 // [128][128]
    float* bs = sh + D_DIM * D_DIM; // [128]

    int tid = threadIdx.x;
    // cooperative load of W: 16384 floats / 256 threads = 16 float4 each
    const float4* Wv = (const float4*)W;
    float4* Wsv = (float4*)Ws;
#pragma unroll
    for (int i = 0; i < 16; i++) Wsv[tid + i * 256] = Wv[tid + i * 256];
    if (tid < D_DIM) bs[tid] = b[tid];
    __syncthreads();

    int warp = tid >> 5;
    int lane = tid & 31;
    int row0 = blockIdx.x * 64 + warp * 8;

    float acc[8][4];
#pragma unroll
    for (int jj = 0; jj < 8; jj++)
#pragma unroll
        for (int c = 0; c < 4; c++) acc[jj][c] = 0.f;

    const float* A = g_agg;
#pragma unroll 4
    for (int k = 0; k < D_DIM; k += 4) {
        float4 a[8];
#pragma unroll
        for (int jj = 0; jj < 8; jj++)
            a[jj] = *(const float4*)(A + (size_t)(row0 + jj) * D_DIM + k);
#pragma unroll
        for (int kk = 0; kk < 4; kk++) {
            float4 w4 = *(const float4*)(Ws + (k + kk) * D_DIM + lane * 4);
#pragma unroll
            for (int jj = 0; jj < 8; jj++) {
                const float* ap = (const float*)&a[jj];
                float av = ap[kk];
                acc[jj][0] = fmaf(av, w4.x, acc[jj][0]);
                acc[jj][1] = fmaf(av, w4.y, acc[jj][1]);
                acc[jj][2] = fmaf(av, w4.z, acc[jj][2]);
                acc[jj][3] = fmaf(av, w4.w, acc[jj][3]);
            }
        }
    }

    float4 bb = *(const float4*)(bs + lane * 4);
#pragma unroll
    for (int jj = 0; jj < 8; jj++) {
        int row = row0 + jj;
        if (row < N) {
            float4 r;
            r.x = fmaxf(acc[jj][0] + bb.x, 0.f);
            r.y = fmaxf(acc[jj][1] + bb.y, 0.f);
            r.z = fmaxf(acc[jj][2] + bb.z, 0.f);
            r.w = fmaxf(acc[jj][3] + bb.w, 0.f);
            *(float4*)(out + (size_t)row * D_DIM + lane * 4) = r;
        }
    }
}

// ---------------------------------------------------------------------------
extern "C" void kernel_launch(void* const* d_in, const int* in_sizes, int n_in,
                              void* d_out, int out_size) {
    const float* feat = (const float*)d_in[0];   // [N,128]
    const int*   src  = (const int*)d_in[1];     // [E]
    const int*   dst  = (const int*)d_in[2];     // [E]
    const float* w    = (const float*)d_in[3];   // [E]
    const float* W    = (const float*)d_in[4];   // [128,128]
    const float* b    = (const float*)d_in[5];   // [128]
    float* out = (float*)d_out;

    const int N = in_sizes[0] / D_DIM;
    const int E = in_sizes[1];

    init_counts_kernel<<<(N + 255) / 256, 256>>>(N);
    hist_kernel<<<(E + 255) / 256, 256>>>(src, E);
    scan_kernel<<<1, 1024>>>(N);
    scatter_kernel<<<(E + 255) / 256, 256>>>(src, dst, w, E);
    aggregate_kernel<<<(N + 7) / 8, 256>>>(feat, N);

    const int smem = (D_DIM * D_DIM + D_DIM) * (int)sizeof(float);  // 66048 B
    cudaFuncSetAttribute(gemm_relu_kernel,
                         cudaFuncAttributeMaxDynamicSharedMemorySize, smem);
    gemm_relu_kernel<<<(N + 63) / 64, 256, smem>>>(W, b, out, N);
}

// round 6
// speedup vs baseline: 1.1044x; 1.1044x over previous
#include <cuda_runtime.h>
#include <cuda_fp16.h>

// Fixed problem shape: N=50000, E=1600000, D=U=128.
#define MAX_N 50048
#define MAX_E 1600000
#define D_DIM 128

// Scratch (__device__ globals; no allocations allowed).
__device__ int    g_counts[MAX_N];
__device__ int    g_offsets[MAX_N + 1];
__device__ int    g_cursor[MAX_N];
__device__ int2   g_edges[MAX_E];                       // (dst, weight bits), CSR by src
__device__ __half g_featH[(size_t)MAX_N * D_DIM];       // fp16 copy of node_features

// ---------------------------------------------------------------------------
__global__ void init_counts_kernel(int N) {
    int i = blockIdx.x * blockDim.x + threadIdx.x;
    if (i < N) g_counts[i] = 0;
}

// fp32 -> fp16 feature table (one float4 -> 4 halves per thread)
__global__ void convert_kernel(const float* __restrict__ feat, int total4) {
    int i = blockIdx.x * blockDim.x + threadIdx.x;
    if (i < total4) {
        float4 v = ((const float4*)feat)[i];
        __half2 h0 = __floats2half2_rn(v.x, v.y);
        __half2 h1 = __floats2half2_rn(v.z, v.w);
        uint2 u;
        *reinterpret_cast<__half2*>(&u.x) = h0;
        *reinterpret_cast<__half2*>(&u.y) = h1;
        ((uint2*)g_featH)[i] = u;
    }
}

// histogram of edge_src, 4 edges/thread
__global__ void hist_kernel(const int* __restrict__ src, int E) {
    int i = (blockIdx.x * blockDim.x + threadIdx.x) * 4;
    if (i + 4 <= E) {
        int4 s = *(const int4*)(src + i);
        atomicAdd(&g_counts[s.x], 1);
        atomicAdd(&g_counts[s.y], 1);
        atomicAdd(&g_counts[s.z], 1);
        atomicAdd(&g_counts[s.w], 1);
    } else {
        for (int j = i; j < E; j++) atomicAdd(&g_counts[src[j]], 1);
    }
}

// single-block exclusive scan (warp-shuffle based, 3 barriers per chunk)
__global__ void scan_kernel(int N) {
    __shared__ int s_warp[32];
    __shared__ int s_carry;
    const int tid = threadIdx.x, lane = tid & 31, wid = tid >> 5;
    const int ITEMS = 16, NT = 1024, CHUNK = NT * ITEMS;

    if (tid == 0) s_carry = 0;
    __syncthreads();

    for (int base = 0; base < N; base += CHUNK) {
        int vals[ITEMS];
        int local = 0;
        int start = base + tid * ITEMS;
#pragma unroll
        for (int i = 0; i < ITEMS; i++) {
            int idx = start + i;
            vals[i] = (idx < N) ? g_counts[idx] : 0;
            local += vals[i];
        }
        // warp inclusive scan of per-thread sums
        int x = local;
#pragma unroll
        for (int off = 1; off < 32; off <<= 1) {
            int y = __shfl_up_sync(0xffffffffu, x, off);
            if (lane >= off) x += y;
        }
        if (lane == 31) s_warp[wid] = x;
        __syncthreads();
        int carry = s_carry;
        if (wid == 0) {
            int v = s_warp[lane];
            int xv = v;
#pragma unroll
            for (int off = 1; off < 32; off <<= 1) {
                int y = __shfl_up_sync(0xffffffffu, xv, off);
                if (lane >= off) xv += y;
            }
            s_warp[lane] = xv - v;  // exclusive warp prefix
        }
        __syncthreads();
        int pre = carry + s_warp[wid] + (x - local);
#pragma unroll
        for (int i = 0; i < ITEMS; i++) {
            int idx = start + i;
            if (idx < N) { g_offsets[idx] = pre; g_cursor[idx] = pre; }
            pre += vals[i];
        }
        __syncthreads();
        // tid 1023 = warp 31 lane 31: carry + excl[31] + inclusive total of warp 31
        if (tid == NT - 1) s_carry = carry + s_warp[31] + x;
    }
    __syncthreads();
    if (tid == 0) g_offsets[N] = s_carry;
}

// scatter edges into CSR order, 2 edges/thread for MLP
__global__ void scatter_kernel(const int* __restrict__ src,
                               const int* __restrict__ dst,
                               const float* __restrict__ w, int E) {
    int i = (blockIdx.x * blockDim.x + threadIdx.x) * 2;
    if (i + 2 <= E) {
        int2   s  = *(const int2*)(src + i);
        int2   d  = *(const int2*)(dst + i);
        float2 ww = *(const float2*)(w + i);
        int p0 = atomicAdd(&g_cursor[s.x], 1);
        int p1 = atomicAdd(&g_cursor[s.y], 1);
        g_edges[p0] = make_int2(d.x, __float_as_int(ww.x));
        g_edges[p1] = make_int2(d.y, __float_as_int(ww.y));
    } else if (i < E) {
        int p = atomicAdd(&g_cursor[src[i]], 1);
        g_edges[p] = make_int2(dst[i], __float_as_int(w[i]));
    }
}

// ---------------------------------------------------------------------------
// Fused: per warp, aggregate 4 node rows (fp16 gather, fp32 accum) into smem,
// then register-blocked 4-row x 4-col GEMM against smem-resident W; relu+bias.
#define ROWS_PER_WARP 4
#define FWARPS 8
#define FTILE (FWARPS * ROWS_PER_WARP)  // 32 nodes per block-tile

__global__ __launch_bounds__(256, 2)
void fused_agg_gemm_kernel(const float* __restrict__ W,
                           const float* __restrict__ b,
                           float* __restrict__ out, int N) {
    extern __shared__ float sh[];
    float* Ws   = sh;                            // [128][128]
    float* bs   = Ws + D_DIM * D_DIM;            // [128]
    float* aggs = bs + D_DIM;                    // [8][4][128]

    const int tid = threadIdx.x;
    // cooperative W load: 16384 floats / 256 threads = 16 float4 each
    const float4* Wv = (const float4*)W;
    float4* Wsv = (float4*)Ws;
#pragma unroll
    for (int i = 0; i < 16; i++) Wsv[tid + i * 256] = Wv[tid + i * 256];
    if (tid < D_DIM) bs[tid] = b[tid];
    __syncthreads();

    const int warp = tid >> 5, lane = tid & 31;
    float* myagg = aggs + warp * ROWS_PER_WARP * D_DIM;
    const uint2* fH = (const uint2*)g_featH;     // 4 halves per uint2

    const int tiles = (N + FTILE - 1) / FTILE;
    for (int t = blockIdx.x; t < tiles; t += gridDim.x) {
        const int base = t * FTILE + warp * ROWS_PER_WARP;

        // ---- gather phase: weighted mean per node row ----
#pragma unroll
        for (int r = 0; r < ROWS_PER_WARP; r++) {
            int node = base + r;
            float ax = 0.f, ay = 0.f, az = 0.f, aw = 0.f, den = 0.f;
            if (node < N) {
                int beg = g_offsets[node], end = g_offsets[node + 1];
                int j = beg;
                for (; j + 2 <= end; j += 2) {
                    int2 e0 = g_edges[j];
                    int2 e1 = g_edges[j + 1];
                    float w0 = __int_as_float(e0.y);
                    float w1 = __int_as_float(e1.y);
                    uint2 h0 = fH[(size_t)e0.x * 32 + lane];
                    uint2 h1 = fH[(size_t)e1.x * 32 + lane];
                    float2 a0 = __half22float2(*reinterpret_cast<__half2*>(&h0.x));
                    float2 a1 = __half22float2(*reinterpret_cast<__half2*>(&h0.y));
                    float2 c0 = __half22float2(*reinterpret_cast<__half2*>(&h1.x));
                    float2 c1 = __half22float2(*reinterpret_cast<__half2*>(&h1.y));
                    ax = fmaf(w0, a0.x, ax); ay = fmaf(w0, a0.y, ay);
                    az = fmaf(w0, a1.x, az); aw = fmaf(w0, a1.y, aw);
                    ax = fmaf(w1, c0.x, ax); ay = fmaf(w1, c0.y, ay);
                    az = fmaf(w1, c1.x, az); aw = fmaf(w1, c1.y, aw);
                    den += w0 + w1;
                }
                if (j < end) {
                    int2 e0 = g_edges[j];
                    float w0 = __int_as_float(e0.y);
                    uint2 h0 = fH[(size_t)e0.x * 32 + lane];
                    float2 a0 = __half22float2(*reinterpret_cast<__half2*>(&h0.x));
                    float2 a1 = __half22float2(*reinterpret_cast<__half2*>(&h0.y));
                    ax = fmaf(w0, a0.x, ax); ay = fmaf(w0, a0.y, ay);
                    az = fmaf(w0, a1.x, az); aw = fmaf(w0, a1.y, aw);
                    den += w0;
                }
                float inv = 1.0f / fmaxf(den, 1e-12f);
                ax *= inv; ay *= inv; az *= inv; aw *= inv;
            }
            *(float4*)(myagg + r * D_DIM + lane * 4) = make_float4(ax, ay, az, aw);
        }
        __syncwarp();

        // ---- GEMM phase: out[4 rows][lane*4..+3] ----
        float4 acc[ROWS_PER_WARP];
#pragma unroll
        for (int r = 0; r < ROWS_PER_WARP; r++) acc[r] = make_float4(0.f, 0.f, 0.f, 0.f);

#pragma unroll 8
        for (int k = 0; k < D_DIM; k += 4) {
            float4 a[ROWS_PER_WARP];
#pragma unroll
            for (int r = 0; r < ROWS_PER_WARP; r++)
                a[r] = *(float4*)(myagg + r * D_DIM + k);   // broadcast LDS.128
#pragma unroll
            for (int kk = 0; kk < 4; kk++) {
                float4 w4 = *(float4*)(Ws + (k + kk) * D_DIM + lane * 4);
#pragma unroll
                for (int r = 0; r < ROWS_PER_WARP; r++) {
                    float av = ((float*)&a[r])[kk];
                    acc[r].x = fmaf(av, w4.x, acc[r].x);
                    acc[r].y = fmaf(av, w4.y, acc[r].y);
                    acc[r].z = fmaf(av, w4.z, acc[r].z);
                    acc[r].w = fmaf(av, w4.w, acc[r].w);
                }
            }
        }

        float4 bb = *(float4*)(bs + lane * 4);
#pragma unroll
        for (int r = 0; r < ROWS_PER_WARP; r++) {
            int row = base + r;
            if (row < N) {
                float4 o;
                o.x = fmaxf(acc[r].x + bb.x, 0.f);
                o.y = fmaxf(acc[r].y + bb.y, 0.f);
                o.z = fmaxf(acc[r].z + bb.z, 0.f);
                o.w = fmaxf(acc[r].w + bb.w, 0.f);
                *(float4*)(out + (size_t)row * D_DIM + lane * 4) = o;
            }
        }
        __syncwarp();   // myagg reuse fence before next tile's gather writes
    }
}

// ---------------------------------------------------------------------------
extern "C" void kernel_launch(void* const* d_in, const int* in_sizes, int n_in,
                              void* d_out, int out_size) {
    const float* feat = (const float*)d_in[0];   // [N,128]
    const int*   src  = (const int*)d_in[1];     // [E]
    const int*   dst  = (const int*)d_in[2];     // [E]
    const float* w    = (const float*)d_in[3];   // [E]
    const float* W    = (const float*)d_in[4];   // [128,128]
    const float* b    = (const float*)d_in[5];   // [128]
    float* out = (float*)d_out;

    const int N = in_sizes[0] / D_DIM;
    const int E = in_sizes[1];

    init_counts_kernel<<<(N + 255) / 256, 256>>>(N);
    {
        int total4 = N * (D_DIM / 4);
        convert_kernel<<<(total4 + 255) / 256, 256>>>(feat, total4);
    }
    hist_kernel<<<((E + 3) / 4 + 255) / 256, 256>>>(src, E);
    scan_kernel<<<1, 1024>>>(N);
    scatter_kernel<<<((E + 1) / 2 + 255) / 256, 256>>>(src, dst, w, E);

    const int smem = (D_DIM * D_DIM + D_DIM +
                      FWARPS * ROWS_PER_WARP * D_DIM) * (int)sizeof(float);  // 82432 B
    cudaFuncSetAttribute(fused_agg_gemm_kernel,
                         cudaFuncAttributeMaxDynamicSharedMemorySize, smem);
    fused_agg_gemm_kernel<<<296, 256, smem>>>(W, b, out, N);
}

// round 7
// speedup vs baseline: 1.3030x; 1.1798x over previous
#include <cuda_runtime.h>
#include <cuda_fp16.h>

// Fixed problem shape: N=50000, E=1600000, D=U=128.
#define MAX_N 50048
#define MAX_E 1600000
#define D_DIM 128

#define SCAN_BLK   256
#define SCAN_ITEMS 16
#define SCAN_TILE  (SCAN_BLK * SCAN_ITEMS)   // 4096
#define MAX_SCAN_BLKS 16                     // ceil(50048/4096)=13

// Scratch (__device__ globals; no allocations allowed).
__device__ int    g_counts[MAX_N];
__device__ int    g_offsets[MAX_N + 1];
__device__ int    g_cursor[MAX_N];
__device__ int    g_partials[MAX_SCAN_BLKS];
__device__ int2   g_edges[MAX_E];                       // (dst, weight bits), CSR by src
__device__ __half g_featH[(size_t)MAX_N * D_DIM];       // fp16 copy of node_features

// ---------------------------------------------------------------------------
__global__ void init_counts_kernel(int N) {
    int i = blockIdx.x * blockDim.x + threadIdx.x;
    if (i < N) g_counts[i] = 0;
}

// fp32 -> fp16 feature table
__global__ void convert_kernel(const float* __restrict__ feat, int total4) {
    int i = blockIdx.x * blockDim.x + threadIdx.x;
    if (i < total4) {
        float4 v = ((const float4*)feat)[i];
        __half2 h0 = __floats2half2_rn(v.x, v.y);
        __half2 h1 = __floats2half2_rn(v.z, v.w);
        uint2 u;
        *reinterpret_cast<__half2*>(&u.x) = h0;
        *reinterpret_cast<__half2*>(&u.y) = h1;
        ((uint2*)g_featH)[i] = u;
    }
}

// histogram of edge_src, 4 edges/thread
__global__ void hist_kernel(const int* __restrict__ src, int E) {
    int i = (blockIdx.x * blockDim.x + threadIdx.x) * 4;
    if (i + 4 <= E) {
        int4 s = *(const int4*)(src + i);
        atomicAdd(&g_counts[s.x], 1);
        atomicAdd(&g_counts[s.y], 1);
        atomicAdd(&g_counts[s.z], 1);
        atomicAdd(&g_counts[s.w], 1);
    } else {
        for (int j = i; j < E; j++) atomicAdd(&g_counts[src[j]], 1);
    }
}

// ---- scan phase 1: per-block partial sums ----
__global__ void scan_partials_kernel(int N) {
    __shared__ int swarp[SCAN_BLK / 32];
    const int tid = threadIdx.x, lane = tid & 31, wid = tid >> 5;
    int start = blockIdx.x * SCAN_TILE + tid * SCAN_ITEMS;
    int local = 0;
    if (start + SCAN_ITEMS <= N) {
#pragma unroll
        for (int v = 0; v < SCAN_ITEMS / 4; v++) {
            int4 c = *(const int4*)(g_counts + start + v * 4);
            local += c.x + c.y + c.z + c.w;
        }
    } else {
        for (int i = start; i < N; i++) local += g_counts[i];
    }
#pragma unroll
    for (int off = 16; off > 0; off >>= 1)
        local += __shfl_down_sync(0xffffffffu, local, off);
    if (lane == 0) swarp[wid] = local;
    __syncthreads();
    if (tid < SCAN_BLK / 32) {
        int v = swarp[tid];
#pragma unroll
        for (int off = (SCAN_BLK / 64); off > 0; off >>= 1)
            v += __shfl_down_sync(0xffu, v, off);
        if (tid == 0) g_partials[blockIdx.x] = v;
    }
}

// ---- scan phase 2: one warp scans the block partials, writes total ----
__global__ void scan_tops_kernel(int nblk, int N) {
    int tid = threadIdx.x;  // 32 threads
    int v = (tid < nblk) ? g_partials[tid] : 0;
    int x = v;
#pragma unroll
    for (int off = 1; off < 32; off <<= 1) {
        int y = __shfl_up_sync(0xffffffffu, x, off);
        if (tid >= off) x += y;
    }
    if (tid < nblk) g_partials[tid] = x - v;   // exclusive prefix
    if (tid == 31) g_offsets[N] = x;           // grand total
}

// ---- scan phase 3: per-block internal scan + write offsets/cursor ----
__global__ void scan_write_kernel(int N) {
    __shared__ int swarp[SCAN_BLK / 32];
    const int tid = threadIdx.x, lane = tid & 31, wid = tid >> 5;
    int start = blockIdx.x * SCAN_TILE + tid * SCAN_ITEMS;
    int vals[SCAN_ITEMS];
    int local = 0;
    if (start + SCAN_ITEMS <= N) {
#pragma unroll
        for (int v = 0; v < SCAN_ITEMS / 4; v++) {
            int4 c = *(const int4*)(g_counts + start + v * 4);
            vals[v * 4 + 0] = c.x; vals[v * 4 + 1] = c.y;
            vals[v * 4 + 2] = c.z; vals[v * 4 + 3] = c.w;
            local += c.x + c.y + c.z + c.w;
        }
    } else {
#pragma unroll
        for (int i = 0; i < SCAN_ITEMS; i++) {
            int idx = start + i;
            vals[i] = (idx < N) ? g_counts[idx] : 0;
            local += vals[i];
        }
    }
    int x = local;
#pragma unroll
    for (int off = 1; off < 32; off <<= 1) {
        int y = __shfl_up_sync(0xffffffffu, x, off);
        if (lane >= off) x += y;
    }
    if (lane == 31) swarp[wid] = x;
    __syncthreads();
    if (wid == 0 && lane < SCAN_BLK / 32) {
        int v = swarp[lane];
        int xv = v;
#pragma unroll
        for (int off = 1; off < SCAN_BLK / 32; off <<= 1) {
            int y = __shfl_up_sync(0xffu, xv, off);
            if (lane >= off) xv += y;
        }
        swarp[lane] = xv - v;   // exclusive warp prefix
    }
    __syncthreads();
    int pre = g_partials[blockIdx.x] + swarp[wid] + (x - local);
    if (start + SCAN_ITEMS <= N) {
#pragma unroll
        for (int i = 0; i < SCAN_ITEMS; i++) {
            g_offsets[start + i] = pre;
            g_cursor[start + i] = pre;
            pre += vals[i];
        }
    } else {
        for (int i = 0; i < SCAN_ITEMS; i++) {
            int idx = start + i;
            if (idx < N) { g_offsets[idx] = pre; g_cursor[idx] = pre; }
            pre += vals[i];
        }
    }
}

// scatter edges into CSR order, 2 edges/thread
__global__ void scatter_kernel(const int* __restrict__ src,
                               const int* __restrict__ dst,
                               const float* __restrict__ w, int E) {
    int i = (blockIdx.x * blockDim.x + threadIdx.x) * 2;
    if (i + 2 <= E) {
        int2   s  = *(const int2*)(src + i);
        int2   d  = *(const int2*)(dst + i);
        float2 ww = *(const float2*)(w + i);
        int p0 = atomicAdd(&g_cursor[s.x], 1);
        int p1 = atomicAdd(&g_cursor[s.y], 1);
        g_edges[p0] = make_int2(d.x, __float_as_int(ww.x));
        g_edges[p1] = make_int2(d.y, __float_as_int(ww.y));
    } else if (i < E) {
        int p = atomicAdd(&g_cursor[src[i]], 1);
        g_edges[p] = make_int2(dst[i], __float_as_int(w[i]));
    }
}

// ---------------------------------------------------------------------------
// Fused aggregate (fp16 gather, fp32 accum) + GEMM + bias + relu.
#define ROWS_PER_WARP 4
#define FWARPS 8
#define FTILE (FWARPS * ROWS_PER_WARP)  // 32 nodes per block-tile

__global__ __launch_bounds__(256, 2)
void fused_agg_gemm_kernel(const float* __restrict__ W,
                           const float* __restrict__ b,
                           float* __restrict__ out, int N) {
    extern __shared__ float sh[];
    float* Ws   = sh;                            // [128][128]
    float* bs   = Ws + D_DIM * D_DIM;            // [128]
    float* aggs = bs + D_DIM;                    // [8][4][128]

    const int tid = threadIdx.x;
    const float4* Wv = (const float4*)W;
    float4* Wsv = (float4*)Ws;
#pragma unroll
    for (int i = 0; i < 16; i++) Wsv[tid + i * 256] = Wv[tid + i * 256];
    if (tid < D_DIM) bs[tid] = b[tid];
    __syncthreads();

    const int warp = tid >> 5, lane = tid & 31;
    float* myagg = aggs + warp * ROWS_PER_WARP * D_DIM;
    const uint2* fH = (const uint2*)g_featH;

    const int tiles = (N + FTILE - 1) / FTILE;
    for (int t = blockIdx.x; t < tiles; t += gridDim.x) {
        const int base = t * FTILE + warp * ROWS_PER_WARP;

        // ---- gather phase: weighted mean per node row, 4-deep MLP ----
#pragma unroll
        for (int r = 0; r < ROWS_PER_WARP; r++) {
            int node = base + r;
            float ax = 0.f, ay = 0.f, az = 0.f, aw = 0.f, den = 0.f;
            if (node < N) {
                int beg = g_offsets[node], end = g_offsets[node + 1];
                int j = beg;
                for (; j + 4 <= end; j += 4) {
                    int2 e0 = g_edges[j + 0];
                    int2 e1 = g_edges[j + 1];
                    int2 e2 = g_edges[j + 2];
                    int2 e3 = g_edges[j + 3];
                    uint2 h0 = fH[(size_t)e0.x * 32 + lane];
                    uint2 h1 = fH[(size_t)e1.x * 32 + lane];
                    uint2 h2 = fH[(size_t)e2.x * 32 + lane];
                    uint2 h3 = fH[(size_t)e3.x * 32 + lane];
                    float w0 = __int_as_float(e0.y);
                    float w1 = __int_as_float(e1.y);
                    float w2 = __int_as_float(e2.y);
                    float w3 = __int_as_float(e3.y);
                    {
                        float2 p = __half22float2(*reinterpret_cast<__half2*>(&h0.x));
                        float2 q = __half22float2(*reinterpret_cast<__half2*>(&h0.y));
                        ax = fmaf(w0, p.x, ax); ay = fmaf(w0, p.y, ay);
                        az = fmaf(w0, q.x, az); aw = fmaf(w0, q.y, aw);
                    }
                    {
                        float2 p = __half22float2(*reinterpret_cast<__half2*>(&h1.x));
                        float2 q = __half22float2(*reinterpret_cast<__half2*>(&h1.y));
                        ax = fmaf(w1, p.x, ax); ay = fmaf(w1, p.y, ay);
                        az = fmaf(w1, q.x, az); aw = fmaf(w1, q.y, aw);
                    }
                    {
                        float2 p = __half22float2(*reinterpret_cast<__half2*>(&h2.x));
                        float2 q = __half22float2(*reinterpret_cast<__half2*>(&h2.y));
                        ax = fmaf(w2, p.x, ax); ay = fmaf(w2, p.y, ay);
                        az = fmaf(w2, q.x, az); aw = fmaf(w2, q.y, aw);
                    }
                    {
                        float2 p = __half22float2(*reinterpret_cast<__half2*>(&h3.x));
                        float2 q = __half22float2(*reinterpret_cast<__half2*>(&h3.y));
                        ax = fmaf(w3, p.x, ax); ay = fmaf(w3, p.y, ay);
                        az = fmaf(w3, q.x, az); aw = fmaf(w3, q.y, aw);
                    }
                    den += (w0 + w1) + (w2 + w3);
                }
                for (; j < end; j++) {
                    int2 e0 = g_edges[j];
                    float w0 = __int_as_float(e0.y);
                    uint2 h0 = fH[(size_t)e0.x * 32 + lane];
                    float2 p = __half22float2(*reinterpret_cast<__half2*>(&h0.x));
                    float2 q = __half22float2(*reinterpret_cast<__half2*>(&h0.y));
                    ax = fmaf(w0, p.x, ax); ay = fmaf(w0, p.y, ay);
                    az = fmaf(w0, q.x, az); aw = fmaf(w0, q.y, aw);
                    den += w0;
                }
                float inv = 1.0f / fmaxf(den, 1e-12f);
                ax *= inv; ay *= inv; az *= inv; aw *= inv;
            }
            *(float4*)(myagg + r * D_DIM + lane * 4) = make_float4(ax, ay, az, aw);
        }
        __syncwarp();

        // ---- GEMM phase ----
        float4 acc[ROWS_PER_WARP];
#pragma unroll
        for (int r = 0; r < ROWS_PER_WARP; r++) acc[r] = make_float4(0.f, 0.f, 0.f, 0.f);

#pragma unroll 8
        for (int k = 0; k < D_DIM; k += 4) {
            float4 a[ROWS_PER_WARP];
#pragma unroll
            for (int r = 0; r < ROWS_PER_WARP; r++)
                a[r] = *(float4*)(myagg + r * D_DIM + k);
#pragma unroll
            for (int kk = 0; kk < 4; kk++) {
                float4 w4 = *(float4*)(Ws + (k + kk) * D_DIM + lane * 4);
#pragma unroll
                for (int r = 0; r < ROWS_PER_WARP; r++) {
                    float av = ((float*)&a[r])[kk];
                    acc[r].x = fmaf(av, w4.x, acc[r].x);
                    acc[r].y = fmaf(av, w4.y, acc[r].y);
                    acc[r].z = fmaf(av, w4.z, acc[r].z);
                    acc[r].w = fmaf(av, w4.w, acc[r].w);
                }
            }
        }

        float4 bb = *(float4*)(bs + lane * 4);
#pragma unroll
        for (int r = 0; r < ROWS_PER_WARP; r++) {
            int row = base + r;
            if (row < N) {
                float4 o;
                o.x = fmaxf(acc[r].x + bb.x, 0.f);
                o.y = fmaxf(acc[r].y + bb.y, 0.f);
                o.z = fmaxf(acc[r].z + bb.z, 0.f);
                o.w = fmaxf(acc[r].w + bb.w, 0.f);
                *(float4*)(out + (size_t)row * D_DIM + lane * 4) = o;
            }
        }
        __syncwarp();
    }
}

// ---------------------------------------------------------------------------
extern "C" void kernel_launch(void* const* d_in, const int* in_sizes, int n_in,
                              void* d_out, int out_size) {
    const float* feat = (const float*)d_in[0];   // [N,128]
    const int*   src  = (const int*)d_in[1];     // [E]
    const int*   dst  = (const int*)d_in[2];     // [E]
    const float* w    = (const float*)d_in[3];   // [E]
    const float* W    = (const float*)d_in[4];   // [128,128]
    const float* b    = (const float*)d_in[5];   // [128]
    float* out = (float*)d_out;

    const int N = in_sizes[0] / D_DIM;
    const int E = in_sizes[1];

    init_counts_kernel<<<(N + 255) / 256, 256>>>(N);
    {
        int total4 = N * (D_DIM / 4);
        convert_kernel<<<(total4 + 255) / 256, 256>>>(feat, total4);
    }
    hist_kernel<<<((E + 3) / 4 + 255) / 256, 256>>>(src, E);

    const int nblk = (N + SCAN_TILE - 1) / SCAN_TILE;   // 13
    scan_partials_kernel<<<nblk, SCAN_BLK>>>(N);
    scan_tops_kernel<<<1, 32>>>(nblk, N);
    scan_write_kernel<<<nblk, SCAN_BLK>>>(N);

    scatter_kernel<<<((E + 1) / 2 + 255) / 256, 256>>>(src, dst, w, E);

    const int smem = (D_DIM * D_DIM + D_DIM +
                      FWARPS * ROWS_PER_WARP * D_DIM) * (int)sizeof(float);  // 82432 B
    cudaFuncSetAttribute(fused_agg_gemm_kernel,
                         cudaFuncAttributeMaxDynamicSharedMemorySize, smem);
    fused_agg_gemm_kernel<<<296, 256, smem>>>(W, b, out, N);
}

// round 8
// speedup vs baseline: 1.3542x; 1.0392x over previous
#include <cuda_runtime.h>
#include <cuda_fp16.h>

// Fixed problem shape: N=50000, E=1600000, D=U=128.
#define MAX_N 50048
#define MAX_E 1600000
#define D_DIM 128

#define SCAN_BLK   256
#define SCAN_ITEMS 16
#define SCAN_TILE  (SCAN_BLK * SCAN_ITEMS)   // 4096
#define MAX_SCAN_BLKS 16

// Packed fp32x2 FMA (Blackwell): one issue slot, two IEEE fp32 FMAs.
#define FMA_F32X2(d, a, b, c) \
    asm("fma.rn.f32x2 %0, %1, %2, %3;" : "=l"(d) : "l"(a), "l"(b), "l"(c))
#define PACK_F32X2(d, lo, hi) \
    asm("mov.b64 %0, {%1, %2};" : "=l"(d) : "f"(lo), "f"(hi))
#define UNPACK_F32X2(lo, hi, s) \
    asm("mov.b64 {%0, %1}, %2;" : "=f"(lo), "=f"(hi) : "l"(s))

// Scratch (__device__ globals; no allocations allowed).
__device__ int    g_counts[MAX_N];
__device__ int    g_offsets[MAX_N + 1];
__device__ int    g_cursor[MAX_N];
__device__ int    g_partials[MAX_SCAN_BLKS];
__device__ int2   g_edges[MAX_E];                       // (dst, weight bits), CSR by src
__device__ __half g_featH[(size_t)MAX_N * D_DIM];       // fp16 copy of node_features

// ---------------------------------------------------------------------------
// fp32 -> fp16 feature table, fused with histogram zeroing (total4 > N).
__global__ void prep_kernel(const float* __restrict__ feat, int total4, int N) {
    int i = blockIdx.x * blockDim.x + threadIdx.x;
    if (i < total4) {
        float4 v = ((const float4*)feat)[i];
        __half2 h0 = __floats2half2_rn(v.x, v.y);
        __half2 h1 = __floats2half2_rn(v.z, v.w);
        uint2 u;
        *reinterpret_cast<__half2*>(&u.x) = h0;
        *reinterpret_cast<__half2*>(&u.y) = h1;
        ((uint2*)g_featH)[i] = u;
    }
    if (i < N) g_counts[i] = 0;
}

// histogram of edge_src, 4 edges/thread
__global__ void hist_kernel(const int* __restrict__ src, int E) {
    int i = (blockIdx.x * blockDim.x + threadIdx.x) * 4;
    if (i + 4 <= E) {
        int4 s = *(const int4*)(src + i);
        atomicAdd(&g_counts[s.x], 1);
        atomicAdd(&g_counts[s.y], 1);
        atomicAdd(&g_counts[s.z], 1);
        atomicAdd(&g_counts[s.w], 1);
    } else {
        for (int j = i; j < E; j++) atomicAdd(&g_counts[src[j]], 1);
    }
}

// ---- scan phase 1: per-block partial sums ----
__global__ void scan_partials_kernel(int N) {
    __shared__ int swarp[SCAN_BLK / 32];
    const int tid = threadIdx.x, lane = tid & 31, wid = tid >> 5;
    int start = blockIdx.x * SCAN_TILE + tid * SCAN_ITEMS;
    int local = 0;
    if (start + SCAN_ITEMS <= N) {
#pragma unroll
        for (int v = 0; v < SCAN_ITEMS / 4; v++) {
            int4 c = *(const int4*)(g_counts + start + v * 4);
            local += c.x + c.y + c.z + c.w;
        }
    } else {
        for (int i = start; i < N; i++) local += g_counts[i];
    }
#pragma unroll
    for (int off = 16; off > 0; off >>= 1)
        local += __shfl_down_sync(0xffffffffu, local, off);
    if (lane == 0) swarp[wid] = local;
    __syncthreads();
    if (tid < SCAN_BLK / 32) {
        int v = swarp[tid];
#pragma unroll
        for (int off = (SCAN_BLK / 64); off > 0; off >>= 1)
            v += __shfl_down_sync(0xffu, v, off);
        if (tid == 0) g_partials[blockIdx.x] = v;
    }
}

// ---- scan phase 2: one warp scans the block partials ----
__global__ void scan_tops_kernel(int nblk, int N) {
    int tid = threadIdx.x;
    int v = (tid < nblk) ? g_partials[tid] : 0;
    int x = v;
#pragma unroll
    for (int off = 1; off < 32; off <<= 1) {
        int y = __shfl_up_sync(0xffffffffu, x, off);
        if (tid >= off) x += y;
    }
    if (tid < nblk) g_partials[tid] = x - v;
    if (tid == 31) g_offsets[N] = x;
}

// ---- scan phase 3: per-block internal scan + write offsets/cursor ----
__global__ void scan_write_kernel(int N) {
    __shared__ int swarp[SCAN_BLK / 32];
    const int tid = threadIdx.x, lane = tid & 31, wid = tid >> 5;
    int start = blockIdx.x * SCAN_TILE + tid * SCAN_ITEMS;
    int vals[SCAN_ITEMS];
    int local = 0;
    if (start + SCAN_ITEMS <= N) {
#pragma unroll
        for (int v = 0; v < SCAN_ITEMS / 4; v++) {
            int4 c = *(const int4*)(g_counts + start + v * 4);
            vals[v * 4 + 0] = c.x; vals[v * 4 + 1] = c.y;
            vals[v * 4 + 2] = c.z; vals[v * 4 + 3] = c.w;
            local += c.x + c.y + c.z + c.w;
        }
    } else {
#pragma unroll
        for (int i = 0; i < SCAN_ITEMS; i++) {
            int idx = start + i;
            vals[i] = (idx < N) ? g_counts[idx] : 0;
            local += vals[i];
        }
    }
    int x = local;
#pragma unroll
    for (int off = 1; off < 32; off <<= 1) {
        int y = __shfl_up_sync(0xffffffffu, x, off);
        if (lane >= off) x += y;
    }
    if (lane == 31) swarp[wid] = x;
    __syncthreads();
    if (wid == 0 && lane < SCAN_BLK / 32) {
        int v = swarp[lane];
        int xv = v;
#pragma unroll
        for (int off = 1; off < SCAN_BLK / 32; off <<= 1) {
            int y = __shfl_up_sync(0xffu, xv, off);
            if (lane >= off) xv += y;
        }
        swarp[lane] = xv - v;
    }
    __syncthreads();
    int pre = g_partials[blockIdx.x] + swarp[wid] + (x - local);
    if (start + SCAN_ITEMS <= N) {
#pragma unroll
        for (int i = 0; i < SCAN_ITEMS; i++) {
            g_offsets[start + i] = pre;
            g_cursor[start + i] = pre;
            pre += vals[i];
        }
    } else {
        for (int i = 0; i < SCAN_ITEMS; i++) {
            int idx = start + i;
            if (idx < N) { g_offsets[idx] = pre; g_cursor[idx] = pre; }
            pre += vals[i];
        }
    }
}

// scatter edges into CSR order, 2 edges/thread
__global__ void scatter_kernel(const int* __restrict__ src,
                               const int* __restrict__ dst,
                               const float* __restrict__ w, int E) {
    int i = (blockIdx.x * blockDim.x + threadIdx.x) * 2;
    if (i + 2 <= E) {
        int2   s  = *(const int2*)(src + i);
        int2   d  = *(const int2*)(dst + i);
        float2 ww = *(const float2*)(w + i);
        int p0 = atomicAdd(&g_cursor[s.x], 1);
        int p1 = atomicAdd(&g_cursor[s.y], 1);
        g_edges[p0] = make_int2(d.x, __float_as_int(ww.x));
        g_edges[p1] = make_int2(d.y, __float_as_int(ww.y));
    } else if (i < E) {
        int p = atomicAdd(&g_cursor[src[i]], 1);
        g_edges[p] = make_int2(dst[i], __float_as_int(w[i]));
    }
}

// ---------------------------------------------------------------------------
// Fused aggregate (fp16 gather, packed fp32 accum) + GEMM (FFMA2) + bias + relu.
#define ROWS_PER_WARP 4
#define FWARPS 8
#define FTILE (FWARPS * ROWS_PER_WARP)  // 32 nodes per block-tile

__global__ __launch_bounds__(256, 2)
void fused_agg_gemm_kernel(const float* __restrict__ W,
                           const float* __restrict__ b,
                           float* __restrict__ out, int N) {
    extern __shared__ float sh[];
    float* Ws   = sh;                            // [128][128]
    float* bs   = Ws + D_DIM * D_DIM;            // [128]
    float* aggs = bs + D_DIM;                    // [8][4][128]

    const int tid = threadIdx.x;
    const float4* Wv = (const float4*)W;
    float4* Wsv = (float4*)Ws;
#pragma unroll
    for (int i = 0; i < 16; i++) Wsv[tid + i * 256] = Wv[tid + i * 256];
    if (tid < D_DIM) bs[tid] = b[tid];
    __syncthreads();

    const int warp = tid >> 5, lane = tid & 31;
    float* myagg = aggs + warp * ROWS_PER_WARP * D_DIM;
    const uint2* fH = (const uint2*)g_featH;

    const int tiles = (N + FTILE - 1) / FTILE;
    for (int t = blockIdx.x; t < tiles; t += gridDim.x) {
        const int base = t * FTILE + warp * ROWS_PER_WARP;

        // ---- gather phase: weighted mean per node row, 4-deep MLP, FFMA2 ----
#pragma unroll
        for (int r = 0; r < ROWS_PER_WARP; r++) {
            int node = base + r;
            unsigned long long sAB = 0ull, sCD = 0ull;   // packed (x,y),(z,w)
            float den = 0.f;
            if (node < N) {
                int beg = g_offsets[node], end = g_offsets[node + 1];
                int j = beg;
                for (; j + 4 <= end; j += 4) {
                    int2 e0 = g_edges[j + 0];
                    int2 e1 = g_edges[j + 1];
                    int2 e2 = g_edges[j + 2];
                    int2 e3 = g_edges[j + 3];
                    uint2 h0 = fH[(size_t)e0.x * 32 + lane];
                    uint2 h1 = fH[(size_t)e1.x * 32 + lane];
                    uint2 h2 = fH[(size_t)e2.x * 32 + lane];
                    uint2 h3 = fH[(size_t)e3.x * 32 + lane];
                    float w0 = __int_as_float(e0.y);
                    float w1 = __int_as_float(e1.y);
                    float w2 = __int_as_float(e2.y);
                    float w3 = __int_as_float(e3.y);
#define EDGE_ACC(hh, wsc) do {                                              \
    float2 p_ = __half22float2(*reinterpret_cast<__half2*>(&(hh).x));       \
    float2 q_ = __half22float2(*reinterpret_cast<__half2*>(&(hh).y));       \
    unsigned long long pp_, qq_, ww_;                                       \
    PACK_F32X2(pp_, p_.x, p_.y);                                            \
    PACK_F32X2(qq_, q_.x, q_.y);                                            \
    PACK_F32X2(ww_, (wsc), (wsc));                                          \
    FMA_F32X2(sAB, ww_, pp_, sAB);                                          \
    FMA_F32X2(sCD, ww_, qq_, sCD);                                          \
} while (0)
                    EDGE_ACC(h0, w0);
                    EDGE_ACC(h1, w1);
                    EDGE_ACC(h2, w2);
                    EDGE_ACC(h3, w3);
                    den += (w0 + w1) + (w2 + w3);
                }
                for (; j < end; j++) {
                    int2 e0 = g_edges[j];
                    float w0 = __int_as_float(e0.y);
                    uint2 h0 = fH[(size_t)e0.x * 32 + lane];
                    EDGE_ACC(h0, w0);
                    den += w0;
                }
#undef EDGE_ACC
            }
            float ax, ay, az, aw;
            UNPACK_F32X2(ax, ay, sAB);
            UNPACK_F32X2(az, aw, sCD);
            float inv = 1.0f / fmaxf(den, 1e-12f);
            *(float4*)(myagg + r * D_DIM + lane * 4) =
                make_float4(ax * inv, ay * inv, az * inv, aw * inv);
        }
        __syncwarp();

        // ---- GEMM phase: packed FFMA2, 4 rows x 4 cols per thread ----
        unsigned long long accA[ROWS_PER_WARP], accB[ROWS_PER_WARP];
#pragma unroll
        for (int r = 0; r < ROWS_PER_WARP; r++) { accA[r] = 0ull; accB[r] = 0ull; }

#pragma unroll 8
        for (int k = 0; k < D_DIM; k += 4) {
            float4 a[ROWS_PER_WARP];
#pragma unroll
            for (int r = 0; r < ROWS_PER_WARP; r++)
                a[r] = *(float4*)(myagg + r * D_DIM + k);
#pragma unroll
            for (int kk = 0; kk < 4; kk++) {
                ulonglong2 wp = *(ulonglong2*)(Ws + (k + kk) * D_DIM + lane * 4);
#pragma unroll
                for (int r = 0; r < ROWS_PER_WARP; r++) {
                    float av = ((float*)&a[r])[kk];
                    unsigned long long avv;
                    PACK_F32X2(avv, av, av);
                    FMA_F32X2(accA[r], avv, wp.x, accA[r]);
                    FMA_F32X2(accB[r], avv, wp.y, accB[r]);
                }
            }
        }

        float4 bb = *(float4*)(bs + lane * 4);
#pragma unroll
        for (int r = 0; r < ROWS_PER_WARP; r++) {
            int row = base + r;
            if (row < N) {
                float ox, oy, oz, ow;
                UNPACK_F32X2(ox, oy, accA[r]);
                UNPACK_F32X2(oz, ow, accB[r]);
                float4 o;
                o.x = fmaxf(ox + bb.x, 0.f);
                o.y = fmaxf(oy + bb.y, 0.f);
                o.z = fmaxf(oz + bb.z, 0.f);
                o.w = fmaxf(ow + bb.w, 0.f);
                *(float4*)(out + (size_t)row * D_DIM + lane * 4) = o;
            }
        }
        __syncwarp();
    }
}

// ---------------------------------------------------------------------------
extern "C" void kernel_launch(void* const* d_in, const int* in_sizes, int n_in,
                              void* d_out, int out_size) {
    const float* feat = (const float*)d_in[0];   // [N,128]
    const int*   src  = (const int*)d_in[1];     // [E]
    const int*   dst  = (const int*)d_in[2];     // [E]
    const float* w    = (const float*)d_in[3];   // [E]
    const float* W    = (const float*)d_in[4];   // [128,128]
    const float* b    = (const float*)d_in[5];   // [128]
    float* out = (float*)d_out;

    const int N = in_sizes[0] / D_DIM;
    const int E = in_sizes[1];

    {
        int total4 = N * (D_DIM / 4);
        prep_kernel<<<(total4 + 255) / 256, 256>>>(feat, total4, N);
    }
    hist_kernel<<<((E + 3) / 4 + 255) / 256, 256>>>(src, E);

    const int nblk = (N + SCAN_TILE - 1) / SCAN_TILE;   // 13
    scan_partials_kernel<<<nblk, SCAN_BLK>>>(N);
    scan_tops_kernel<<<1, 32>>>(nblk, N);
    scan_write_kernel<<<nblk, SCAN_BLK>>>(N);

    scatter_kernel<<<((E + 1) / 2 + 255) / 256, 256>>>(src, dst, w, E);

    const int smem = (D_DIM * D_DIM + D_DIM +
                      FWARPS * ROWS_PER_WARP * D_DIM) * (int)sizeof(float);  // 82432 B
    cudaFuncSetAttribute(fused_agg_gemm_kernel,
                         cudaFuncAttributeMaxDynamicSharedMemorySize, smem);
    fused_agg_gemm_kernel<<<296, 256, smem>>>(W, b, out, N);
}

// round 10
// speedup vs baseline: 1.4022x; 1.0355x over previous
#include <cuda_runtime.h>
#include <cuda_fp16.h>

// Fixed problem shape: N=50000, E=1600000, D=U=128.
#define MAX_N 50048
#define MAX_E 1600000
#define D_DIM 128

#define SCAN_BLK   256
#define SCAN_ITEMS 16
#define SCAN_TILE  (SCAN_BLK * SCAN_ITEMS)   // 4096
#define MAX_SCAN_BLKS 16

// Packed fp32x2 FMA (Blackwell): one issue slot, two IEEE fp32 FMAs.
#define FMA_F32X2(d, a, b, c) \
    asm("fma.rn.f32x2 %0, %1, %2, %3;" : "=l"(d) : "l"(a), "l"(b), "l"(c))
#define PACK_F32X2(d, lo, hi) \
    asm("mov.b64 %0, {%1, %2};" : "=l"(d) : "f"(lo), "f"(hi))
#define UNPACK_F32X2(lo, hi, s) \
    asm("mov.b64 {%0, %1}, %2;" : "=f"(lo), "=f"(hi) : "l"(s))

// Scratch (__device__ globals; no allocations allowed).
__device__ int    g_counts[MAX_N];
__device__ int    g_offsets[MAX_N + 1];
__device__ int    g_cursor[MAX_N];
__device__ int    g_partials[MAX_SCAN_BLKS];
__device__ int2   g_edges[MAX_E];                       // (dst, weight bits), CSR by src
__device__ __half g_featH[(size_t)MAX_N * D_DIM];       // fp16 copy of node_features

// ---------------------------------------------------------------------------
// fp32 -> fp16 feature table, fused with histogram zeroing (total4 > N).
__global__ void prep_kernel(const float* __restrict__ feat, int total4, int N) {
    int i = blockIdx.x * blockDim.x + threadIdx.x;
    if (i < total4) {
        float4 v = ((const float4*)feat)[i];
        __half2 h0 = __floats2half2_rn(v.x, v.y);
        __half2 h1 = __floats2half2_rn(v.z, v.w);
        uint2 u;
        *reinterpret_cast<__half2*>(&u.x) = h0;
        *reinterpret_cast<__half2*>(&u.y) = h1;
        ((uint2*)g_featH)[i] = u;
    }
    if (i < N) g_counts[i] = 0;
}

// histogram of edge_src, 4 edges/thread
__global__ void hist_kernel(const int* __restrict__ src, int E) {
    int i = (blockIdx.x * blockDim.x + threadIdx.x) * 4;
    if (i + 4 <= E) {
        int4 s = *(const int4*)(src + i);
        atomicAdd(&g_counts[s.x], 1);
        atomicAdd(&g_counts[s.y], 1);
        atomicAdd(&g_counts[s.z], 1);
        atomicAdd(&g_counts[s.w], 1);
    } else {
        for (int j = i; j < E; j++) atomicAdd(&g_counts[src[j]], 1);
    }
}

// ---- scan phase 1: per-block partial sums ----
__global__ void scan_partials_kernel(int N) {
    __shared__ int swarp[SCAN_BLK / 32];
    const int tid = threadIdx.x, lane = tid & 31, wid = tid >> 5;
    int start = blockIdx.x * SCAN_TILE + tid * SCAN_ITEMS;
    int local = 0;
    if (start + SCAN_ITEMS <= N) {
#pragma unroll
        for (int v = 0; v < SCAN_ITEMS / 4; v++) {
            int4 c = *(const int4*)(g_counts + start + v * 4);
            local += c.x + c.y + c.z + c.w;
        }
    } else {
        for (int i = start; i < N; i++) local += g_counts[i];
    }
#pragma unroll
    for (int off = 16; off > 0; off >>= 1)
        local += __shfl_down_sync(0xffffffffu, local, off);
    if (lane == 0) swarp[wid] = local;
    __syncthreads();
    if (tid < SCAN_BLK / 32) {
        int v = swarp[tid];
#pragma unroll
        for (int off = (SCAN_BLK / 64); off > 0; off >>= 1)
            v += __shfl_down_sync(0xffu, v, off);
        if (tid == 0) g_partials[blockIdx.x] = v;
    }
}

// ---- scan phase 2: one warp scans the block partials ----
__global__ void scan_tops_kernel(int nblk, int N) {
    int tid = threadIdx.x;
    int v = (tid < nblk) ? g_partials[tid] : 0;
    int x = v;
#pragma unroll
    for (int off = 1; off < 32; off <<= 1) {
        int y = __shfl_up_sync(0xffffffffu, x, off);
        if (tid >= off) x += y;
    }
    if (tid < nblk) g_partials[tid] = x - v;
    if (tid == 31) g_offsets[N] = x;
}

// ---- scan phase 3: per-block internal scan + write offsets/cursor ----
__global__ void scan_write_kernel(int N) {
    __shared__ int swarp[SCAN_BLK / 32];
    const int tid = threadIdx.x, lane = tid & 31, wid = tid >> 5;
    int start = blockIdx.x * SCAN_TILE + tid * SCAN_ITEMS;
    int vals[SCAN_ITEMS];
    int local = 0;
    if (start + SCAN_ITEMS <= N) {
#pragma unroll
        for (int v = 0; v < SCAN_ITEMS / 4; v++) {
            int4 c = *(const int4*)(g_counts + start + v * 4);
            vals[v * 4 + 0] = c.x; vals[v * 4 + 1] = c.y;
            vals[v * 4 + 2] = c.z; vals[v * 4 + 3] = c.w;
            local += c.x + c.y + c.z + c.w;
        }
    } else {
#pragma unroll
        for (int i = 0; i < SCAN_ITEMS; i++) {
            int idx = start + i;
            vals[i] = (idx < N) ? g_counts[idx] : 0;
            local += vals[i];
        }
    }
    int x = local;
#pragma unroll
    for (int off = 1; off < 32; off <<= 1) {
        int y = __shfl_up_sync(0xffffffffu, x, off);
        if (lane >= off) x += y;
    }
    if (lane == 31) swarp[wid] = x;
    __syncthreads();
    if (wid == 0 && lane < SCAN_BLK / 32) {
        int v = swarp[lane];
        int xv = v;
#pragma unroll
        for (int off = 1; off < SCAN_BLK / 32; off <<= 1) {
            int y = __shfl_up_sync(0xffu, xv, off);
            if (lane >= off) xv += y;
        }
        swarp[lane] = xv - v;
    }
    __syncthreads();
    int pre = g_partials[blockIdx.x] + swarp[wid] + (x - local);
    if (start + SCAN_ITEMS <= N) {
#pragma unroll
        for (int i = 0; i < SCAN_ITEMS; i++) {
            g_offsets[start + i] = pre;
            g_cursor[start + i] = pre;
            pre += vals[i];
        }
    } else {
        for (int i = 0; i < SCAN_ITEMS; i++) {
            int idx = start + i;
            if (idx < N) { g_offsets[idx] = pre; g_cursor[idx] = pre; }
            pre += vals[i];
        }
    }
}

// scatter edges into CSR order, 4 edges/thread for atomic/store ILP
__global__ void scatter_kernel(const int* __restrict__ src,
                               const int* __restrict__ dst,
                               const float* __restrict__ w, int E) {
    int i = (blockIdx.x * blockDim.x + threadIdx.x) * 4;
    if (i + 4 <= E) {
        int4   s  = *(const int4*)(src + i);
        int4   d  = *(const int4*)(dst + i);
        float4 ww = *(const float4*)(w + i);
        int p0 = atomicAdd(&g_cursor[s.x], 1);
        int p1 = atomicAdd(&g_cursor[s.y], 1);
        int p2 = atomicAdd(&g_cursor[s.z], 1);
        int p3 = atomicAdd(&g_cursor[s.w], 1);
        g_edges[p0] = make_int2(d.x, __float_as_int(ww.x));
        g_edges[p1] = make_int2(d.y, __float_as_int(ww.y));
        g_edges[p2] = make_int2(d.z, __float_as_int(ww.z));
        g_edges[p3] = make_int2(d.w, __float_as_int(ww.w));
    } else {
        for (int j = i; j < E; j++) {
            int p = atomicAdd(&g_cursor[src[j]], 1);
            g_edges[p] = make_int2(dst[j], __float_as_int(w[j]));
        }
    }
}

// ---------------------------------------------------------------------------
// Fused aggregate (fp16 gather, depth-2 pipelined) + GEMM (FFMA2) + bias + relu.
#define ROWS_PER_WARP 4
#define FWARPS 8
#define FTILE (FWARPS * ROWS_PER_WARP)  // 32 nodes per block-tile

__global__ __launch_bounds__(256, 2)
void fused_agg_gemm_kernel(const float* __restrict__ W,
                           const float* __restrict__ b,
                           float* __restrict__ out, int N) {
    extern __shared__ float sh[];
    float* Ws   = sh;                            // [128][128]
    float* bs   = Ws + D_DIM * D_DIM;            // [128]
    float* aggs = bs + D_DIM;                    // [8][4][128]

    const int tid = threadIdx.x;
    const float4* Wv = (const float4*)W;
    float4* Wsv = (float4*)Ws;
#pragma unroll
    for (int i = 0; i < 16; i++) Wsv[tid + i * 256] = Wv[tid + i * 256];
    if (tid < D_DIM) bs[tid] = b[tid];
    __syncthreads();

    const int warp = tid >> 5, lane = tid & 31;
    float* myagg = aggs + warp * ROWS_PER_WARP * D_DIM;
    const uint2* fH = (const uint2*)g_featH;

    const int tiles = (N + FTILE - 1) / FTILE;
    for (int t = blockIdx.x; t < tiles; t += gridDim.x) {
        const int base = t * FTILE + warp * ROWS_PER_WARP;

        // ---- gather phase: weighted mean per node row, depth-2 pipeline ----
#pragma unroll
        for (int r = 0; r < ROWS_PER_WARP; r++) {
            int node = base + r;
            unsigned long long sAB = 0ull, sCD = 0ull;   // packed (x,y),(z,w)
            float den = 0.f;
            if (node < N) {
                const int beg = g_offsets[node], end = g_offsets[node + 1];
                const int nch = (end - beg + 3) >> 2;    // masked 4-edge chunks
                if (nch > 0) {
                    // masked edge-chunk load: OOB lanes get (dst=0, w=0)
#define LDE(a0, a1, a2, a3, jj) do {                                          \
    a0 = ((jj) + 0 < end) ? g_edges[(jj) + 0] : make_int2(0, 0);              \
    a1 = ((jj) + 1 < end) ? g_edges[(jj) + 1] : make_int2(0, 0);              \
    a2 = ((jj) + 2 < end) ? g_edges[(jj) + 2] : make_int2(0, 0);              \
    a3 = ((jj) + 3 < end) ? g_edges[(jj) + 3] : make_int2(0, 0);              \
} while (0)
#define LDH(x0, x1, x2, x3, a0, a1, a2, a3) do {                              \
    x0 = fH[(size_t)(a0).x * 32 + lane];                                      \
    x1 = fH[(size_t)(a1).x * 32 + lane];                                      \
    x2 = fH[(size_t)(a2).x * 32 + lane];                                      \
    x3 = fH[(size_t)(a3).x * 32 + lane];                                      \
} while (0)
#define EDGE_ACC(hh, wsc) do {                                                \
    float2 p_ = __half22float2(*reinterpret_cast<__half2*>(&(hh).x));         \
    float2 q_ = __half22float2(*reinterpret_cast<__half2*>(&(hh).y));         \
    unsigned long long pp_, qq_, ww_;                                         \
    PACK_F32X2(pp_, p_.x, p_.y);                                              \
    PACK_F32X2(qq_, q_.x, q_.y);                                              \
    PACK_F32X2(ww_, (wsc), (wsc));                                            \
    FMA_F32X2(sAB, ww_, pp_, sAB);                                            \
    FMA_F32X2(sCD, ww_, qq_, sCD);                                            \
} while (0)
#define ACC4() do {                                                           \
    float w0_ = __int_as_float(e0.y), w1_ = __int_as_float(e1.y);             \
    float w2_ = __int_as_float(e2.y), w3_ = __int_as_float(e3.y);             \
    EDGE_ACC(h0, w0_); EDGE_ACC(h1, w1_);                                     \
    EDGE_ACC(h2, w2_); EDGE_ACC(h3, w3_);                                     \
    den += (w0_ + w1_) + (w2_ + w3_);                                         \
} while (0)
                    int2 e0, e1, e2, e3;      // edges: chunk c (being accumulated)
                    int2 f0, f1, f2, f3;      // edges: chunk c+1 (features pending)
                    uint2 h0, h1, h2, h3;     // features: chunk c
                    int j = beg;
                    LDE(e0, e1, e2, e3, j);               // chunk 0 edges
                    LDH(h0, h1, h2, h3, e0, e1, e2, e3);  // chunk 0 features
                    j += 4;
                    if (nch > 1) LDE(f0, f1, f2, f3, j);  // chunk 1 edges
                    for (int c = 0; c + 2 < nch; c++) {
                        j += 4;
                        int2 g0, g1, g2, g3;
                        LDE(g0, g1, g2, g3, j);           // chunk c+2 edges
                        uint2 n0, n1, n2, n3;
                        LDH(n0, n1, n2, n3, f0, f1, f2, f3);  // chunk c+1 feats
                        ACC4();                            // accumulate chunk c
                        e0 = f0; e1 = f1; e2 = f2; e3 = f3;
                        f0 = g0; f1 = g1; f2 = g2; f3 = g3;
                        h0 = n0; h1 = n1; h2 = n2; h3 = n3;
                    }
                    if (nch > 1) {
                        uint2 n0, n1, n2, n3;
                        LDH(n0, n1, n2, n3, f0, f1, f2, f3);  // last chunk feats
                        ACC4();                                // chunk nch-2
                        e0 = f0; e1 = f1; e2 = f2; e3 = f3;
                        h0 = n0; h1 = n1; h2 = n2; h3 = n3;
                    }
                    ACC4();                                    // last chunk
#undef ACC4
#undef EDGE_ACC
#undef LDH
#undef LDE
                }
            }
            float ax, ay, az, aw;
            UNPACK_F32X2(ax, ay, sAB);
            UNPACK_F32X2(az, aw, sCD);
            float inv = 1.0f / fmaxf(den, 1e-12f);
            *(float4*)(myagg + r * D_DIM + lane * 4) =
                make_float4(ax * inv, ay * inv, az * inv, aw * inv);
        }
        __syncwarp();

        // ---- GEMM phase: packed FFMA2, 4 rows x 4 cols per thread ----
        unsigned long long accA[ROWS_PER_WARP], accB[ROWS_PER_WARP];
#pragma unroll
        for (int r = 0; r < ROWS_PER_WARP; r++) { accA[r] = 0ull; accB[r] = 0ull; }

#pragma unroll 8
        for (int k = 0; k < D_DIM; k += 4) {
            float4 a[ROWS_PER_WARP];
#pragma unroll
            for (int r = 0; r < ROWS_PER_WARP; r++)
                a[r] = *(float4*)(myagg + r * D_DIM + k);
#pragma unroll
            for (int kk = 0; kk < 4; kk++) {
                ulonglong2 wp = *(ulonglong2*)(Ws + (k + kk) * D_DIM + lane * 4);
#pragma unroll
                for (int r = 0; r < ROWS_PER_WARP; r++) {
                    float av = ((float*)&a[r])[kk];
                    unsigned long long avv;
                    PACK_F32X2(avv, av, av);
                    FMA_F32X2(accA[r], avv, wp.x, accA[r]);
                    FMA_F32X2(accB[r], avv, wp.y, accB[r]);
                }
            }
        }

        float4 bb = *(float4*)(bs + lane * 4);
#pragma unroll
        for (int r = 0; r < ROWS_PER_WARP; r++) {
            int row = base + r;
            if (row < N) {
                float ox, oy, oz, ow;
                UNPACK_F32X2(ox, oy, accA[r]);
                UNPACK_F32X2(oz, ow, accB[r]);
                float4 o;
                o.x = fmaxf(ox + bb.x, 0.f);
                o.y = fmaxf(oy + bb.y, 0.f);
                o.z = fmaxf(oz + bb.z, 0.f);
                o.w = fmaxf(ow + bb.w, 0.f);
                *(float4*)(out + (size_t)row * D_DIM + lane * 4) = o;
            }
        }
        __syncwarp();
    }
}

// ---------------------------------------------------------------------------
extern "C" void kernel_launch(void* const* d_in, const int* in_sizes, int n_in,
                              void* d_out, int out_size) {
    const float* feat = (const float*)d_in[0];   // [N,128]
    const int*   src  = (const int*)d_in[1];     // [E]
    const int*   dst  = (const int*)d_in[2];     // [E]
    const float* w    = (const float*)d_in[3];   // [E]
    const float* W    = (const float*)d_in[4];   // [128,128]
    const float* b    = (const float*)d_in[5];   // [128]
    float* out = (float*)d_out;

    const int N = in_sizes[0] / D_DIM;
    const int E = in_sizes[1];

    {
        int total4 = N * (D_DIM / 4);
        prep_kernel<<<(total4 + 255) / 256, 256>>>(feat, total4, N);
    }
    hist_kernel<<<((E + 3) / 4 + 255) / 256, 256>>>(src, E);

    const int nblk = (N + SCAN_TILE - 1) / SCAN_TILE;   // 13
    scan_partials_kernel<<<nblk, SCAN_BLK>>>(N);
    scan_tops_kernel<<<1, 32>>>(nblk, N);
    scan_write_kernel<<<nblk, SCAN_BLK>>>(N);

    scatter_kernel<<<((E + 3) / 4 + 255) / 256, 256>>>(src, dst, w, E);

    const int smem = (D_DIM * D_DIM + D_DIM +
                      FWARPS * ROWS_PER_WARP * D_DIM) * (int)sizeof(float);  // 82432 B
    cudaFuncSetAttribute(fused_agg_gemm_kernel,
                         cudaFuncAttributeMaxDynamicSharedMemorySize, smem);
    fused_agg_gemm_kernel<<<296, 256, smem>>>(W, b, out, N);
}